// round 6
// baseline (speedup 1.0000x reference)
#include <cuda_runtime.h>
#include <math.h>

// Problem constants
constexpr int B_   = 16;
constexpr int H_   = 16;
constexpr int HD_  = 128;
constexpr int D_   = 2048;
constexpr int SPAST = 4096;
constexpr int SPLITS = 8;
constexpr int CHUNK  = 512;   // SPAST / SPLITS
constexpr float SCALING = 0.08838834764831845f;  // 128^-0.5

// Scratch (static device globals — no allocation allowed)
__device__ float g_q[B_ * D_];
__device__ float g_attn[B_ * D_];
__device__ float g_pm[B_ * H_ * SPLITS];
__device__ float g_pl[B_ * H_ * SPLITS];
__device__ float g_pacc[B_ * H_ * SPLITS * HD_];

struct GemvArgs {
    const float* W[3];
    const float* bias[3];
    float*       out[3];
    float        scale[3];
};

// Packed f32x2 FMA: d = a * b + d (elementwise on the two packed floats).
// ptxas never emits FFMA2 from C++; this PTX is the only route (SASS_QUICKREF).
__device__ __forceinline__ void fma2(unsigned long long& d,
                                     unsigned long long a,
                                     unsigned long long b) {
    asm("fma.rn.f32x2 %0, %1, %2, %0;" : "+l"(d) : "l"(a), "l"(b));
}

__device__ __forceinline__ float unpack_sum(unsigned long long v) {
    float lo, hi;
    asm("mov.b64 {%0, %1}, %2;" : "=f"(lo), "=f"(hi) : "l"(v));
    return lo + hi;
}

// ---------------------------------------------------------------------------
// GEMV (no split-K): out[b,o] = (sum_d x[b,d]*W[o,d] + bias[o]) * scale.
// 128-thread blocks; each warp owns 4 consecutive output rows and register-
// blocks all 16 batches with packed f32x2 accumulators (halves FFMA count —
// the kernel is FMA-issue-bound, not DRAM-bound, at batch=16).
// Weight loads are software-pipelined one iteration ahead.
// ---------------------------------------------------------------------------
__global__ __launch_bounds__(128) void gemv_kernel(const float* __restrict__ x,
                                                   GemvArgs a) {
    int gw   = (blockIdx.x * 128 + threadIdx.x) >> 5;  // global warp id
    int lane = threadIdx.x & 31;
    int row0 = gw * 4;
    int mi   = row0 >> 11;      // which matrix (rows are 2048 per matrix)
    int o0   = row0 & 2047;

    const ulonglong2* W = (const ulonglong2*)a.W[mi];
    const ulonglong2* X = (const ulonglong2*)x;

    unsigned long long acc[4][16];
#pragma unroll
    for (int r = 0; r < 4; r++)
#pragma unroll
        for (int b = 0; b < 16; b++) acc[r][b] = 0ull;

    // Prefetch iteration 0 weights (16B granules; 512 granules per row).
    int d4 = lane;
    ulonglong2 w0 = __ldcs(&W[(size_t)(o0 + 0) * 512 + d4]);
    ulonglong2 w1 = __ldcs(&W[(size_t)(o0 + 1) * 512 + d4]);
    ulonglong2 w2 = __ldcs(&W[(size_t)(o0 + 2) * 512 + d4]);
    ulonglong2 w3 = __ldcs(&W[(size_t)(o0 + 3) * 512 + d4]);

#pragma unroll
    for (int ii = 0; ii < 16; ii++) {
        ulonglong2 c0 = w0, c1 = w1, c2 = w2, c3 = w3;
        int dcur = d4;
        if (ii + 1 < 16) {
            d4 += 32;
            w0 = __ldcs(&W[(size_t)(o0 + 0) * 512 + d4]);
            w1 = __ldcs(&W[(size_t)(o0 + 1) * 512 + d4]);
            w2 = __ldcs(&W[(size_t)(o0 + 2) * 512 + d4]);
            w3 = __ldcs(&W[(size_t)(o0 + 3) * 512 + d4]);
        }
#pragma unroll
        for (int b = 0; b < 16; b++) {
            ulonglong2 xv = X[b * 512 + dcur];
            fma2(acc[0][b], c0.x, xv.x);  fma2(acc[0][b], c0.y, xv.y);
            fma2(acc[1][b], c1.x, xv.x);  fma2(acc[1][b], c1.y, xv.y);
            fma2(acc[2][b], c2.x, xv.x);  fma2(acc[2][b], c2.y, xv.y);
            fma2(acc[3][b], c3.x, xv.x);  fma2(acc[3][b], c3.y, xv.y);
        }
    }

    // Collapse packed halves, then warp-reduce each of the 64 sums.
    float accf[4][16];
#pragma unroll
    for (int r = 0; r < 4; r++)
#pragma unroll
        for (int b = 0; b < 16; b++) {
            float v = unpack_sum(acc[r][b]);
            v += __shfl_xor_sync(0xffffffffu, v, 16);
            v += __shfl_xor_sync(0xffffffffu, v, 8);
            v += __shfl_xor_sync(0xffffffffu, v, 4);
            v += __shfl_xor_sync(0xffffffffu, v, 2);
            v += __shfl_xor_sync(0xffffffffu, v, 1);
            accf[r][b] = v;
        }

    const float* bias = a.bias[mi];
    float*       out  = a.out[mi];
    float        sc   = a.scale[mi];
#pragma unroll
    for (int r = 0; r < 4; r++) {
        float bb = bias[o0 + r];
#pragma unroll
        for (int b = 0; b < 16; b++)
            if (lane == b)
                out[b * D_ + o0 + r] = (accf[r][b] + bb) * sc;
    }
}

// ---------------------------------------------------------------------------
// Split-S flash-decode attention partials (proven round-5 structure).
// grid = (256 bh, 8 splits), block = 256 (8 warps). Warp-per-row online
// softmax; each lane owns 4 contiguous head-dim elements (float4).
// K/V are a 1 GB single-use stream: __ldcs keeps them out of L2's way.
// ---------------------------------------------------------------------------
__global__ __launch_bounds__(256) void attn_partial_kernel(
    const float* __restrict__ pk, const float* __restrict__ pv,
    const float* __restrict__ mask,
    const float* __restrict__ knew, const float* __restrict__ vnew) {
    int bh    = blockIdx.x;
    int split = blockIdx.y;
    int b     = bh >> 4;
    int h     = bh & 15;
    int warp  = threadIdx.x >> 5;
    int lane  = threadIdx.x & 31;

    const float4* q4p = (const float4*)(g_q + b * D_ + h * HD_);
    float4 q4 = q4p[lane];  // q pre-scaled by SCALING

    size_t base = ((size_t)b * SPAST) * D_ + h * HD_;

    float  m = -1e30f, l = 0.f;
    float4 acc = make_float4(0.f, 0.f, 0.f, 0.f);

    int s0 = split * CHUNK + warp;
    int s_end = split * CHUNK + CHUNK;

#pragma unroll 4
    for (int s = s0; s < s_end; s += 8) {
        const float4* kr = (const float4*)(pk + base + (size_t)s * D_);
        const float4* vr = (const float4*)(pv + base + (size_t)s * D_);
        float4 k4 = __ldcs(&kr[lane]);
        float4 v4 = __ldcs(&vr[lane]);
        float sc = k4.x * q4.x + k4.y * q4.y + k4.z * q4.z + k4.w * q4.w;
        sc += __shfl_xor_sync(0xffffffffu, sc, 16);
        sc += __shfl_xor_sync(0xffffffffu, sc, 8);
        sc += __shfl_xor_sync(0xffffffffu, sc, 4);
        sc += __shfl_xor_sync(0xffffffffu, sc, 2);
        sc += __shfl_xor_sync(0xffffffffu, sc, 1);
        sc += mask[s];
        float nm   = fmaxf(m, sc);
        float corr = __expf(m - nm);
        float p    = __expf(sc - nm);
        m = nm;
        l = l * corr + p;
        acc.x = acc.x * corr + p * v4.x;
        acc.y = acc.y * corr + p * v4.y;
        acc.z = acc.z * corr + p * v4.z;
        acc.w = acc.w * corr + p * v4.w;
    }

    // The new token (s = 4096) lives in the last split, handled by warp 0.
    if (split == SPLITS - 1 && warp == 0) {
        const float4* kr = (const float4*)(knew + b * D_ + h * HD_);
        const float4* vr = (const float4*)(vnew + b * D_ + h * HD_);
        float4 k4 = kr[lane];
        float4 v4 = vr[lane];
        float sc = k4.x * q4.x + k4.y * q4.y + k4.z * q4.z + k4.w * q4.w;
        sc += __shfl_xor_sync(0xffffffffu, sc, 16);
        sc += __shfl_xor_sync(0xffffffffu, sc, 8);
        sc += __shfl_xor_sync(0xffffffffu, sc, 4);
        sc += __shfl_xor_sync(0xffffffffu, sc, 2);
        sc += __shfl_xor_sync(0xffffffffu, sc, 1);
        sc += mask[SPAST];
        float nm   = fmaxf(m, sc);
        float corr = __expf(m - nm);
        float p    = __expf(sc - nm);
        m = nm;
        l = l * corr + p;
        acc.x = acc.x * corr + p * v4.x;
        acc.y = acc.y * corr + p * v4.y;
        acc.z = acc.z * corr + p * v4.z;
        acc.w = acc.w * corr + p * v4.w;
    }

    // Combine the 8 warps of this block.
    __shared__ float  sm_m[8], sm_l[8];
    __shared__ float4 sm_acc[8][32];
    sm_acc[warp][lane] = acc;
    if (lane == 0) { sm_m[warp] = m; sm_l[warp] = l; }
    __syncthreads();

    if (threadIdx.x < HD_) {
        int d = threadIdx.x;
        float M = -1e30f;
#pragma unroll
        for (int w = 0; w < 8; w++) M = fmaxf(M, sm_m[w]);
        float L = 0.f, A = 0.f;
        const float* accf = (const float*)sm_acc;
#pragma unroll
        for (int w = 0; w < 8; w++) {
            float e = __expf(sm_m[w] - M);
            L += sm_l[w] * e;
            A += accf[w * HD_ + d] * e;
        }
        int idx = bh * SPLITS + split;
        g_pacc[idx * HD_ + d] = A;
        if (d == 0) { g_pm[idx] = M; g_pl[idx] = L; }
    }
}

// ---------------------------------------------------------------------------
// Combine the 8 split partials per (b,h) into the attention output vector.
// ---------------------------------------------------------------------------
__global__ __launch_bounds__(128) void attn_combine_kernel() {
    int bh = blockIdx.x;
    int d  = threadIdx.x;
    float M = -1e30f;
#pragma unroll
    for (int i = 0; i < SPLITS; i++) M = fmaxf(M, g_pm[bh * SPLITS + i]);
    float L = 0.f, A = 0.f;
#pragma unroll
    for (int i = 0; i < SPLITS; i++) {
        float e = __expf(g_pm[bh * SPLITS + i] - M);
        L += g_pl[bh * SPLITS + i] * e;
        A += g_pacc[(bh * SPLITS + i) * HD_ + d] * e;
    }
    int b = bh >> 4, h = bh & 15;
    g_attn[b * D_ + h * HD_ + d] = A / L;
}

// ---------------------------------------------------------------------------
extern "C" void kernel_launch(void* const* d_in, const int* in_sizes, int n_in,
                              void* d_out, int out_size) {
    const float* hs   = (const float*)d_in[0];
    const float* pk   = (const float*)d_in[1];
    const float* pv   = (const float*)d_in[2];
    const float* mask = (const float*)d_in[3];
    const float* Wq   = (const float*)d_in[4];
    const float* bq   = (const float*)d_in[5];
    const float* Wk   = (const float*)d_in[6];
    const float* bk   = (const float*)d_in[7];
    const float* Wv   = (const float*)d_in[8];
    const float* bv   = (const float*)d_in[9];
    const float* Wo   = (const float*)d_in[10];
    const float* bo   = (const float*)d_in[11];

    float* out  = (float*)d_out;          // [0, 32768): attn_output
    float* knew = out + B_ * D_;          // [32768, 65536): new_key
    float* vnew = out + 2 * B_ * D_;      // [65536, 98304): new_value

    float* qptr;  cudaGetSymbolAddress((void**)&qptr, g_q);
    float* aptr;  cudaGetSymbolAddress((void**)&aptr, g_attn);

    // 1. Fused QKV projection, direct store (no init, no atomics).
    //    6144 rows / (4 warps * 4 rows) = 384 blocks.
    GemvArgs a;
    a.W[0] = Wq; a.bias[0] = bq; a.out[0] = qptr; a.scale[0] = SCALING;
    a.W[1] = Wk; a.bias[1] = bk; a.out[1] = knew; a.scale[1] = 1.f;
    a.W[2] = Wv; a.bias[2] = bv; a.out[2] = vnew; a.scale[2] = 1.f;
    gemv_kernel<<<384, 128>>>(hs, a);

    // 2. Split-S attention partials (the HBM-bound 1.07 GB stream).
    attn_partial_kernel<<<dim3(B_ * H_, SPLITS), 256>>>(pk, pv, mask, knew, vnew);

    // 3. Combine partials.
    attn_combine_kernel<<<B_ * H_, 128>>>();

    // 4. Output projection: 2048 rows -> 128 blocks.
    GemvArgs ao;
    ao.W[0] = Wo; ao.bias[0] = bo; ao.out[0] = out; ao.scale[0] = 1.f;
    ao.W[1] = Wo; ao.bias[1] = bo; ao.out[1] = out; ao.scale[1] = 1.f;
    ao.W[2] = Wo; ao.bias[2] = bo; ao.out[2] = out; ao.scale[2] = 1.f;
    gemv_kernel<<<128, 128>>>(aptr, ao);
}

// round 7
// speedup vs baseline: 1.1602x; 1.1602x over previous
#include <cuda_runtime.h>
#include <math.h>

// Problem constants
constexpr int B_   = 16;
constexpr int H_   = 16;
constexpr int HD_  = 128;
constexpr int D_   = 2048;
constexpr int SPAST = 4096;
constexpr int SPLITS = 8;
constexpr int CHUNK  = 512;   // SPAST / SPLITS
constexpr float SCALING = 0.08838834764831845f;  // 128^-0.5

// Scratch (static device globals — no allocation allowed)
__device__ float g_q[B_ * D_];
__device__ float g_attn[B_ * D_];
__device__ float g_pm[B_ * H_ * SPLITS];
__device__ float g_pl[B_ * H_ * SPLITS];
__device__ float g_pacc[B_ * H_ * SPLITS * HD_];

struct GemvArgs {
    const float* W[3];
    const float* bias[3];
    float*       out[3];
    float        scale[3];
};

// ---------------------------------------------------------------------------
// Split-K GEMV (round-5 proven float4 version).
// KSPLIT=1: direct store of (acc + bias) * scale  (no init pass, no atomics).
// KSPLIT>1: atomicAdd partials into a bias-preseeded output.
// 128-thread blocks (3 blocks/SM at ~141 regs -> 12 warps/SM).
// Each warp owns 4 consecutive output rows, register-blocks all 16 batches;
// weight loads software-pipelined one iteration ahead.
// ---------------------------------------------------------------------------
template <int KSPLIT>
__global__ __launch_bounds__(128) void gemv_kernel(const float* __restrict__ x,
                                                   GemvArgs a) {
    int gw   = (blockIdx.x * 128 + threadIdx.x) >> 5;  // global warp id
    int lane = threadIdx.x & 31;
    int row0 = gw * 4;
    int mi   = row0 >> 11;      // which matrix (rows are 2048 per matrix)
    int o0   = row0 & 2047;

    const float4* W = (const float4*)a.W[mi];
    const float4* X = (const float4*)x;

    float acc[4][16];
#pragma unroll
    for (int r = 0; r < 4; r++)
#pragma unroll
        for (int b = 0; b < 16; b++) acc[r][b] = 0.f;

    constexpr int ITERS = 16 / KSPLIT;
    int i0 = blockIdx.y * ITERS;

    // Prefetch iteration 0 weights.
    int d4 = i0 * 32 + lane;
    float4 w0 = __ldcs(&W[(size_t)(o0 + 0) * 512 + d4]);
    float4 w1 = __ldcs(&W[(size_t)(o0 + 1) * 512 + d4]);
    float4 w2 = __ldcs(&W[(size_t)(o0 + 2) * 512 + d4]);
    float4 w3 = __ldcs(&W[(size_t)(o0 + 3) * 512 + d4]);

#pragma unroll
    for (int ii = 0; ii < ITERS; ii++) {
        float4 c0 = w0, c1 = w1, c2 = w2, c3 = w3;
        int dcur = d4;
        if (ii + 1 < ITERS) {
            d4 += 32;
            w0 = __ldcs(&W[(size_t)(o0 + 0) * 512 + d4]);
            w1 = __ldcs(&W[(size_t)(o0 + 1) * 512 + d4]);
            w2 = __ldcs(&W[(size_t)(o0 + 2) * 512 + d4]);
            w3 = __ldcs(&W[(size_t)(o0 + 3) * 512 + d4]);
        }
#pragma unroll
        for (int b = 0; b < 16; b++) {
            float4 xv = X[b * 512 + dcur];
            acc[0][b] += c0.x * xv.x + c0.y * xv.y + c0.z * xv.z + c0.w * xv.w;
            acc[1][b] += c1.x * xv.x + c1.y * xv.y + c1.z * xv.z + c1.w * xv.w;
            acc[2][b] += c2.x * xv.x + c2.y * xv.y + c2.z * xv.z + c2.w * xv.w;
            acc[3][b] += c3.x * xv.x + c3.y * xv.y + c3.z * xv.z + c3.w * xv.w;
        }
    }

    // Warp-reduce each of the 64 partial sums
#pragma unroll
    for (int r = 0; r < 4; r++)
#pragma unroll
        for (int b = 0; b < 16; b++) {
            float v = acc[r][b];
            v += __shfl_xor_sync(0xffffffffu, v, 16);
            v += __shfl_xor_sync(0xffffffffu, v, 8);
            v += __shfl_xor_sync(0xffffffffu, v, 4);
            v += __shfl_xor_sync(0xffffffffu, v, 2);
            v += __shfl_xor_sync(0xffffffffu, v, 1);
            acc[r][b] = v;
        }

    float* out = a.out[mi];
    float  sc  = a.scale[mi];
    if (KSPLIT == 1) {
        const float* bias = a.bias[mi];
#pragma unroll
        for (int r = 0; r < 4; r++) {
            float bb = bias[o0 + r];
#pragma unroll
            for (int b = 0; b < 16; b++)
                if (lane == b)
                    out[b * D_ + o0 + r] = (acc[r][b] + bb) * sc;
        }
    } else {
#pragma unroll
        for (int r = 0; r < 4; r++)
#pragma unroll
            for (int b = 0; b < 16; b++)
                if (lane == b)
                    atomicAdd(&out[b * D_ + o0 + r], acc[r][b] * sc);
    }
}

// ---------------------------------------------------------------------------
// Split-S flash-decode attention partials (proven round-5 structure,
// untouched). grid = (256 bh, 8 splits), block = 256 (8 warps).
// Warp-per-row online softmax; each lane owns 4 head-dim elements (float4).
// K/V are a 1 GB single-use stream: __ldcs keeps them out of L2's way.
// ---------------------------------------------------------------------------
__global__ __launch_bounds__(256) void attn_partial_kernel(
    const float* __restrict__ pk, const float* __restrict__ pv,
    const float* __restrict__ mask,
    const float* __restrict__ knew, const float* __restrict__ vnew) {
    int bh    = blockIdx.x;
    int split = blockIdx.y;
    int b     = bh >> 4;
    int h     = bh & 15;
    int warp  = threadIdx.x >> 5;
    int lane  = threadIdx.x & 31;

    const float4* q4p = (const float4*)(g_q + b * D_ + h * HD_);
    float4 q4 = q4p[lane];  // q pre-scaled by SCALING

    size_t base = ((size_t)b * SPAST) * D_ + h * HD_;

    float  m = -1e30f, l = 0.f;
    float4 acc = make_float4(0.f, 0.f, 0.f, 0.f);

    int s0 = split * CHUNK + warp;
    int s_end = split * CHUNK + CHUNK;

#pragma unroll 4
    for (int s = s0; s < s_end; s += 8) {
        const float4* kr = (const float4*)(pk + base + (size_t)s * D_);
        const float4* vr = (const float4*)(pv + base + (size_t)s * D_);
        float4 k4 = __ldcs(&kr[lane]);
        float4 v4 = __ldcs(&vr[lane]);
        float sc = k4.x * q4.x + k4.y * q4.y + k4.z * q4.z + k4.w * q4.w;
        sc += __shfl_xor_sync(0xffffffffu, sc, 16);
        sc += __shfl_xor_sync(0xffffffffu, sc, 8);
        sc += __shfl_xor_sync(0xffffffffu, sc, 4);
        sc += __shfl_xor_sync(0xffffffffu, sc, 2);
        sc += __shfl_xor_sync(0xffffffffu, sc, 1);
        sc += mask[s];
        float nm   = fmaxf(m, sc);
        float corr = __expf(m - nm);
        float p    = __expf(sc - nm);
        m = nm;
        l = l * corr + p;
        acc.x = acc.x * corr + p * v4.x;
        acc.y = acc.y * corr + p * v4.y;
        acc.z = acc.z * corr + p * v4.z;
        acc.w = acc.w * corr + p * v4.w;
    }

    // The new token (s = 4096) lives in the last split, handled by warp 0.
    if (split == SPLITS - 1 && warp == 0) {
        const float4* kr = (const float4*)(knew + b * D_ + h * HD_);
        const float4* vr = (const float4*)(vnew + b * D_ + h * HD_);
        float4 k4 = kr[lane];
        float4 v4 = vr[lane];
        float sc = k4.x * q4.x + k4.y * q4.y + k4.z * q4.z + k4.w * q4.w;
        sc += __shfl_xor_sync(0xffffffffu, sc, 16);
        sc += __shfl_xor_sync(0xffffffffu, sc, 8);
        sc += __shfl_xor_sync(0xffffffffu, sc, 4);
        sc += __shfl_xor_sync(0xffffffffu, sc, 2);
        sc += __shfl_xor_sync(0xffffffffu, sc, 1);
        sc += mask[SPAST];
        float nm   = fmaxf(m, sc);
        float corr = __expf(m - nm);
        float p    = __expf(sc - nm);
        m = nm;
        l = l * corr + p;
        acc.x = acc.x * corr + p * v4.x;
        acc.y = acc.y * corr + p * v4.y;
        acc.z = acc.z * corr + p * v4.z;
        acc.w = acc.w * corr + p * v4.w;
    }

    // Combine the 8 warps of this block.
    __shared__ float  sm_m[8], sm_l[8];
    __shared__ float4 sm_acc[8][32];
    sm_acc[warp][lane] = acc;
    if (lane == 0) { sm_m[warp] = m; sm_l[warp] = l; }
    __syncthreads();

    if (threadIdx.x < HD_) {
        int d = threadIdx.x;
        float M = -1e30f;
#pragma unroll
        for (int w = 0; w < 8; w++) M = fmaxf(M, sm_m[w]);
        float L = 0.f, A = 0.f;
        const float* accf = (const float*)sm_acc;
#pragma unroll
        for (int w = 0; w < 8; w++) {
            float e = __expf(sm_m[w] - M);
            L += sm_l[w] * e;
            A += accf[w * HD_ + d] * e;
        }
        int idx = bh * SPLITS + split;
        g_pacc[idx * HD_ + d] = A;
        if (d == 0) { g_pm[idx] = M; g_pl[idx] = L; }
    }
}

// ---------------------------------------------------------------------------
// Combine the 8 split partials per (b,h) AND seed the final output buffer
// with the Wo bias (256 blocks * 128 threads == 32768 == |out|), so the Wo
// split-K gemv can pure-atomicAdd with no separate init kernel.
// ---------------------------------------------------------------------------
__global__ __launch_bounds__(128) void attn_combine_kernel(
    float* __restrict__ out, const float* __restrict__ bo) {
    int bh = blockIdx.x;
    int d  = threadIdx.x;

    int oidx = bh * HD_ + d;          // [0, 32768)
    out[oidx] = bo[oidx & (D_ - 1)];  // seed Wo bias

    float M = -1e30f;
#pragma unroll
    for (int i = 0; i < SPLITS; i++) M = fmaxf(M, g_pm[bh * SPLITS + i]);
    float L = 0.f, A = 0.f;
#pragma unroll
    for (int i = 0; i < SPLITS; i++) {
        float e = __expf(g_pm[bh * SPLITS + i] - M);
        L += g_pl[bh * SPLITS + i] * e;
        A += g_pacc[(bh * SPLITS + i) * HD_ + d] * e;
    }
    int b = bh >> 4, h = bh & 15;
    g_attn[b * D_ + h * HD_ + d] = A / L;
}

// ---------------------------------------------------------------------------
extern "C" void kernel_launch(void* const* d_in, const int* in_sizes, int n_in,
                              void* d_out, int out_size) {
    const float* hs   = (const float*)d_in[0];
    const float* pk   = (const float*)d_in[1];
    const float* pv   = (const float*)d_in[2];
    const float* mask = (const float*)d_in[3];
    const float* Wq   = (const float*)d_in[4];
    const float* bq   = (const float*)d_in[5];
    const float* Wk   = (const float*)d_in[6];
    const float* bk   = (const float*)d_in[7];
    const float* Wv   = (const float*)d_in[8];
    const float* bv   = (const float*)d_in[9];
    const float* Wo   = (const float*)d_in[10];
    const float* bo   = (const float*)d_in[11];

    float* out  = (float*)d_out;          // [0, 32768): attn_output
    float* knew = out + B_ * D_;          // [32768, 65536): new_key
    float* vnew = out + 2 * B_ * D_;      // [65536, 98304): new_value

    float* qptr;  cudaGetSymbolAddress((void**)&qptr, g_q);
    float* aptr;  cudaGetSymbolAddress((void**)&aptr, g_attn);

    // 1. Fused QKV projection, direct bias store (no init, no atomics).
    //    6144 rows / (4 warps * 4 rows) = 384 blocks, one wave at 3/SM.
    GemvArgs a;
    a.W[0] = Wq; a.bias[0] = bq; a.out[0] = qptr; a.scale[0] = SCALING;
    a.W[1] = Wk; a.bias[1] = bk; a.out[1] = knew; a.scale[1] = 1.f;
    a.W[2] = Wv; a.bias[2] = bv; a.out[2] = vnew; a.scale[2] = 1.f;
    gemv_kernel<1><<<384, 128>>>(hs, a);

    // 2. Split-S attention partials (the HBM-bound 1.07 GB stream).
    attn_partial_kernel<<<dim3(B_ * H_, SPLITS), 256>>>(pk, pv, mask, knew, vnew);

    // 3. Combine partials + seed out with Wo bias.
    attn_combine_kernel<<<B_ * H_, 128>>>(out, bo);

    // 4. Output projection: split-K=4 -> 512 blocks over 2048 rows.
    GemvArgs ao;
    ao.W[0] = Wo; ao.bias[0] = bo; ao.out[0] = out; ao.scale[0] = 1.f;
    ao.W[1] = Wo; ao.bias[1] = bo; ao.out[1] = out; ao.scale[1] = 1.f;
    ao.W[2] = Wo; ao.bias[2] = bo; ao.out[2] = out; ao.scale[2] = 1.f;
    gemv_kernel<4><<<dim3(128, 4), 128>>>(aptr, ao);
}